// round 13
// baseline (speedup 1.0000x reference)
#include <cuda_runtime.h>
#include <cuda_fp16.h>
#include <cstdint>
#include <cstddef>

// Problem constants
#define BATCH   8
#define SEQ     4096
#define DMODEL  1024
#define NHEAD   16
#define DHEAD   64
#define TOKENS  (BATCH * SEQ)            // 32768
#define GK      DMODEL                   // GEMM K = 1024

// ---------------------------------------------------------------------------
// Static scratch (no cudaMalloc allowed)
// ---------------------------------------------------------------------------
__device__ __half g_qh [(size_t)TOKENS * DMODEL];
__device__ __half g_kh [(size_t)TOKENS * DMODEL];
__device__ __half g_vh [(size_t)TOKENS * DMODEL];
__device__ __half g_xh [(size_t)TOKENS * DMODEL];
__device__ __half g_ch [(size_t)TOKENS * DMODEL];
__device__ __half g_wh [4][(size_t)DMODEL * DMODEL];   // wq|wk|wv|wo fp16

// ---------------------------------------------------------------------------
__device__ __forceinline__ uint32_t smem_u32(const void* p) {
    uint32_t a;
    asm("{ .reg .u64 t; cvta.to.shared.u64 t, %1; cvt.u32.u64 %0, t; }"
        : "=r"(a) : "l"(p));
    return a;
}

__device__ __forceinline__ void ldsm_x4(uint32_t (&r)[4], uint32_t addr) {
    asm volatile("ldmatrix.sync.aligned.m8n8.x4.shared.b16 {%0,%1,%2,%3}, [%4];"
                 : "=r"(r[0]), "=r"(r[1]), "=r"(r[2]), "=r"(r[3]) : "r"(addr));
}

__device__ __forceinline__ void mma_f16(float (&d)[4], const uint32_t (&a)[4],
                                        const uint32_t* b) {
    asm volatile(
        "mma.sync.aligned.m16n8k16.row.col.f32.f16.f16.f32 "
        "{%0,%1,%2,%3}, {%4,%5,%6,%7}, {%8,%9}, {%0,%1,%2,%3};"
        : "+f"(d[0]), "+f"(d[1]), "+f"(d[2]), "+f"(d[3])
        : "r"(a[0]), "r"(a[1]), "r"(a[2]), "r"(a[3]), "r"(b[0]), "r"(b[1]));
}

__device__ __forceinline__ void cp16(uint32_t dst, const void* src) {
    asm volatile("cp.async.cg.shared.global [%0], [%1], 16;"
                 :: "r"(dst), "l"(src));
}

// ---------------------------------------------------------------------------
// fp32 -> fp16 converts
// ---------------------------------------------------------------------------
__global__ void conv_f16(const float* __restrict__ src,
                         __half* __restrict__ dst, int n4) {
    int i = blockIdx.x * blockDim.x + threadIdx.x;
    if (i >= n4) return;
    float4 v = reinterpret_cast<const float4*>(src)[i];
    __half h[4] = { __float2half_rn(v.x), __float2half_rn(v.y),
                    __float2half_rn(v.z), __float2half_rn(v.w) };
    reinterpret_cast<uint2*>(dst)[i] = *reinterpret_cast<uint2*>(h);
}

__global__ void conv_w4(const float* __restrict__ w0, const float* __restrict__ w1,
                        const float* __restrict__ w2, const float* __restrict__ w3,
                        __half* __restrict__ dst, int n4) {
    int i = blockIdx.x * blockDim.x + threadIdx.x;
    if (i >= n4) return;
    const float* src = (blockIdx.y == 0) ? w0 : (blockIdx.y == 1) ? w1
                     : (blockIdx.y == 2) ? w2 : w3;
    float4 v = reinterpret_cast<const float4*>(src)[i];
    __half h[4] = { __float2half_rn(v.x), __float2half_rn(v.y),
                    __float2half_rn(v.z), __float2half_rn(v.w) };
    reinterpret_cast<uint2*>(dst + (size_t)blockIdx.y * DMODEL * DMODEL)[i] =
        *reinterpret_cast<uint2*>(h);
}

// ---------------------------------------------------------------------------
// HMMA GEMM core: CTA 256x128, K-chunk 64, 3-stage cp.async pipeline,
// register-level fragment double-buffering (ldsm for ks+1 before MMAs of ks).
// 8 warps (4 M x 2 N), warp tile 64x64, mma.sync m16n8k16.
// ---------------------------------------------------------------------------
#define CHUNK       64
#define NCHUNK      (GK / CHUNK)          // 16
#define A_BYTES     32768                 // 256 x 128B
#define W_BYTES     16384                 // 128 x 128B
#define STAGE_BYTES (A_BYTES + W_BYTES)   // 49152
#define NSTAGE      3
#define SMEM_DYN    (NSTAGE * STAGE_BYTES)  // 147456

template <typename OutT>
__device__ __forceinline__ void gemm_core(
    const __half* __restrict__ Ah, const __half* __restrict__ Wh,
    const float* __restrict__ bias, OutT* __restrict__ C,
    int colN0, size_t rowM0, char* smem)
{
    const uint32_t sb = smem_u32(smem);
    const int tid  = threadIdx.x;
    const int wid  = tid >> 5;
    const int lane = tid & 31;
    const int wm   = wid & 3;
    const int wn   = wid >> 2;

    const char* srcA = (const char*)(Ah + rowM0 * GK);
    const char* srcW = (const char*)(Wh + (size_t)colN0 * GK);

    const int a_row = wm * 64 + (lane & 15);
    const int a_ku  = lane >> 4;
    const int b_row = wn * 64 + (lane & 7) + ((lane >> 4) << 3);
    const int b_ku  = (lane >> 3) & 1;

    float acc[4][8][4];
#pragma unroll
    for (int mi = 0; mi < 4; mi++)
#pragma unroll
        for (int nf = 0; nf < 8; nf++)
#pragma unroll
            for (int j = 0; j < 4; j++) acc[mi][nf][j] = 0.f;

    auto load_chunk = [&](int c) {
        const uint32_t stage = sb + (c % NSTAGE) * STAGE_BYTES;
        const int k0b = c * CHUNK * 2;
#pragma unroll
        for (int u2 = 0; u2 < 12; u2++) {
            const int g = tid + u2 * 256;
            if (g < 2048) {
                const int row = g >> 3;
                const int u   = g & 7;
                const uint32_t dst = stage + row * 128 + ((u ^ (row & 7)) << 4);
                cp16(dst, srcA + (size_t)row * 2048 + k0b + u * 16);
            } else {
                const int w   = g - 2048;
                const int row = w >> 3;
                const int u   = w & 7;
                const uint32_t dst = stage + A_BYTES + row * 128
                                   + ((u ^ (row & 7)) << 4);
                cp16(dst, srcW + (size_t)row * 2048 + k0b + u * 16);
            }
        }
        asm volatile("cp.async.commit_group;" ::: "memory");
    };

    // fragment loader for one ks step
    auto ld_frags = [&](uint32_t stage, int ks,
                        uint32_t (&ah)[4][4], uint32_t (&bh)[4][4]) {
        const uint32_t t_ah = stage;
        const uint32_t t_wh = stage + A_BYTES;
#pragma unroll
        for (int mi = 0; mi < 4; mi++) {
            const int row = a_row + mi * 16;
            const int u   = ks * 2 + a_ku;
            ldsm_x4(ah[mi], t_ah + row * 128 + ((u ^ (row & 7)) << 4));
        }
#pragma unroll
        for (int gg = 0; gg < 4; gg++) {
            const int row = b_row + gg * 16;
            const int u   = ks * 2 + b_ku;
            ldsm_x4(bh[gg], t_wh + row * 128 + ((u ^ (row & 7)) << 4));
        }
    };

    load_chunk(0);
    load_chunk(1);

    uint32_t ah[2][4][4], bh[2][4][4];

    for (int c = 0; c < NCHUNK; c++) {
        if (c + 2 < NCHUNK) {
            load_chunk(c + 2);
            asm volatile("cp.async.wait_group 2;" ::: "memory");
        } else if (c + 1 < NCHUNK) {
            asm volatile("cp.async.wait_group 1;" ::: "memory");
        } else {
            asm volatile("cp.async.wait_group 0;" ::: "memory");
        }
        __syncthreads();

        const uint32_t stage = sb + (c % NSTAGE) * STAGE_BYTES;

        ld_frags(stage, 0, ah[0], bh[0]);
#pragma unroll
        for (int ks = 0; ks < 4; ks++) {
            const int cur = ks & 1;
            if (ks < 3) ld_frags(stage, ks + 1, ah[cur ^ 1], bh[cur ^ 1]);
#pragma unroll
            for (int mi = 0; mi < 4; mi++)
#pragma unroll
                for (int gg = 0; gg < 4; gg++)
#pragma unroll
                    for (int sub = 0; sub < 2; sub++)
                        mma_f16(acc[mi][gg * 2 + sub], ah[cur][mi],
                                &bh[cur][gg][sub * 2]);
        }
        __syncthreads();
    }

#pragma unroll
    for (int mi = 0; mi < 4; mi++) {
#pragma unroll
        for (int nf = 0; nf < 8; nf++) {
            const int col = colN0 + wn * 64 + nf * 8 + (lane & 3) * 2;
            const float2 bv2 = *reinterpret_cast<const float2*>(bias + col);
#pragma unroll
            for (int rh = 0; rh < 2; rh++) {
                const size_t row = rowM0 + wm * 64 + mi * 16 + (lane >> 2) + rh * 8;
                const float ox = acc[mi][nf][rh * 2 + 0] + bv2.x;
                const float oy = acc[mi][nf][rh * 2 + 1] + bv2.y;
                if constexpr (sizeof(OutT) == 2) {
                    *reinterpret_cast<__half2*>((__half*)C + row * DMODEL + col) =
                        __floats2half2_rn(ox, oy);
                } else {
                    float2 o; o.x = ox; o.y = oy;
                    *reinterpret_cast<float2*>((float*)C + row * DMODEL + col) = o;
                }
            }
        }
    }
}

__global__ __launch_bounds__(256, 1) void gemm_qkv(
    const __half* __restrict__ Ah, const __half* __restrict__ Wh,
    const float* __restrict__ bq, const float* __restrict__ bk,
    const float* __restrict__ bv,
    __half* __restrict__ Q, __half* __restrict__ K, __half* __restrict__ V)
{
    extern __shared__ __align__(1024) char smem[];
    const int wsel  = blockIdx.x >> 3;
    const int colN0 = (blockIdx.x & 7) * 128;
    const size_t rowM0 = (size_t)blockIdx.y * 256;
    const size_t WN = (size_t)DMODEL * DMODEL;

    const float* bias = (wsel == 0) ? bq : (wsel == 1) ? bk : bv;
    __half*      C    = (wsel == 0) ? Q  : (wsel == 1) ? K  : V;
    gemm_core<__half>(Ah, Wh + wsel * WN, bias, C, colN0, rowM0, smem);
}

__global__ __launch_bounds__(256, 1) void gemm_out(
    const __half* __restrict__ Ah, const __half* __restrict__ Wh,
    const float* __restrict__ bias, float* __restrict__ C)
{
    extern __shared__ __align__(1024) char smem[];
    gemm_core<float>(Ah, Wh, bias, C, blockIdx.x * 128,
                     (size_t)blockIdx.y * 256, smem);
}

// ---------------------------------------------------------------------------
// Per-token attention — vectorized shared accesses (unchanged from R12).
// ---------------------------------------------------------------------------
__global__ __launch_bounds__(256) void attn_kernel(
    const __half* __restrict__ Q, const __half* __restrict__ K,
    const __half* __restrict__ V, __half* __restrict__ CH)
{
    const size_t base = (size_t)blockIdx.x * DMODEL;
    __shared__ __half sq[DMODEL];
    __shared__ __half sk[DMODEL];
    __shared__ __half sv[DMODEL];
    __shared__ float  sp[NHEAD][NHEAD];

    const int tid = threadIdx.x;
    if (tid < 128) {
        reinterpret_cast<uint4*>(sq)[tid] = reinterpret_cast<const uint4*>(Q + base)[tid];
        reinterpret_cast<uint4*>(sk)[tid] = reinterpret_cast<const uint4*>(K + base)[tid];
    } else {
        reinterpret_cast<uint4*>(sv)[tid - 128] =
            reinterpret_cast<const uint4*>(V + base)[tid - 128];
    }
    __syncthreads();

    const __half2* sq2 = reinterpret_cast<const __half2*>(sq);
    const __half2* sk2 = reinterpret_cast<const __half2*>(sk);
    const __half2* sv2 = reinterpret_cast<const __half2*>(sv);

    const int h    = tid >> 4;
    const int g    = tid & 15;
    const int lane = tid & 31;
    float s = 0.f;
#pragma unroll
    for (int jj = 0; jj < 32; jj++) {
        const int j = (jj + lane) & 31;
        const float2 a = __half22float2(sq2[h * 32 + j]);
        const float2 b = __half22float2(sk2[g * 32 + j]);
        s = fmaf(a.x, b.x, s);
        s = fmaf(a.y, b.y, s);
    }
    s *= 0.125f;

    float m = s;
#pragma unroll
    for (int o = 8; o > 0; o >>= 1) m = fmaxf(m, __shfl_xor_sync(0xFFFFFFFFu, m, o, 16));
    const float e = __expf(s - m);
    float sum = e;
#pragma unroll
    for (int o = 8; o > 0; o >>= 1) sum += __shfl_xor_sync(0xFFFFFFFFu, sum, o, 16);
    sp[h][g] = e / sum;
    __syncthreads();

    __half2* out2 = reinterpret_cast<__half2*>(CH + base);
#pragma unroll
    for (int r = 0; r < 2; r++) {
        const int idx2 = tid + r * 256;
        const int hh   = idx2 >> 5;
        const int d2   = idx2 & 31;
        float pr[16];
        *reinterpret_cast<float4*>(&pr[0])  = *reinterpret_cast<const float4*>(&sp[hh][0]);
        *reinterpret_cast<float4*>(&pr[4])  = *reinterpret_cast<const float4*>(&sp[hh][4]);
        *reinterpret_cast<float4*>(&pr[8])  = *reinterpret_cast<const float4*>(&sp[hh][8]);
        *reinterpret_cast<float4*>(&pr[12]) = *reinterpret_cast<const float4*>(&sp[hh][12]);
        float ax = 0.f, ay = 0.f;
#pragma unroll
        for (int gg = 0; gg < 16; gg++) {
            const float2 v = __half22float2(sv2[gg * 32 + d2]);
            ax = fmaf(pr[gg], v.x, ax);
            ay = fmaf(pr[gg], v.y, ay);
        }
        out2[hh * 32 + d2] = __floats2half2_rn(ax, ay);
    }
}

// ---------------------------------------------------------------------------
extern "C" void kernel_launch(void* const* d_in, const int* in_sizes, int n_in,
                              void* d_out, int out_size)
{
    const float* x  = (const float*)d_in[0];
    const float* wq = (const float*)d_in[1];
    const float* bq = (const float*)d_in[2];
    const float* wk = (const float*)d_in[3];
    const float* bk = (const float*)d_in[4];
    const float* wv = (const float*)d_in[5];
    const float* bv = (const float*)d_in[6];
    const float* wo = (const float*)d_in[7];
    const float* bo = (const float*)d_in[8];
    float* out = (float*)d_out;

    __half *qh, *kh, *vh, *xh, *ch, *wh;
    cudaGetSymbolAddress((void**)&qh, g_qh);
    cudaGetSymbolAddress((void**)&kh, g_kh);
    cudaGetSymbolAddress((void**)&vh, g_vh);
    cudaGetSymbolAddress((void**)&xh, g_xh);
    cudaGetSymbolAddress((void**)&ch, g_ch);
    cudaGetSymbolAddress((void**)&wh, g_wh);

    cudaFuncSetAttribute(gemm_qkv,
                         cudaFuncAttributeMaxDynamicSharedMemorySize, SMEM_DYN);
    cudaFuncSetAttribute(gemm_out,
                         cudaFuncAttributeMaxDynamicSharedMemorySize, SMEM_DYN);

    const size_t WN = (size_t)DMODEL * DMODEL;
    const int nx4 = (TOKENS * DMODEL) / 4;
    const int nw4 = (int)(WN / 4);

    conv_f16<<<(nx4 + 255) / 256, 256>>>(x, xh, nx4);
    dim3 wgrid((nw4 + 255) / 256, 4);
    conv_w4<<<wgrid, 256>>>(wq, wk, wv, wo, wh, nw4);

    dim3 qkvgrid(24, TOKENS / 256);
    gemm_qkv<<<qkvgrid, 256, SMEM_DYN>>>(xh, wh, bq, bk, bv, qh, kh, vh);

    attn_kernel<<<TOKENS, 256>>>(qh, kh, vh, ch);

    dim3 ogrid(DMODEL / 128, TOKENS / 256);
    gemm_out<<<ogrid, 256, SMEM_DYN>>>(ch, wh + 3 * WN, bo, out);
}

// round 16
// speedup vs baseline: 1.1361x; 1.1361x over previous
#include <cuda_runtime.h>
#include <cuda_fp16.h>
#include <cstdint>
#include <cstddef>

// Problem constants
#define BATCH   8
#define SEQ     4096
#define DMODEL  1024
#define NHEAD   16
#define DHEAD   64
#define TOKENS  (BATCH * SEQ)            // 32768
#define GK      DMODEL                   // GEMM K = 1024

// ---------------------------------------------------------------------------
// Static scratch (no cudaMalloc allowed)
// ---------------------------------------------------------------------------
__device__ __half g_qh [(size_t)TOKENS * DMODEL];
__device__ __half g_kh [(size_t)TOKENS * DMODEL];
__device__ __half g_vh [(size_t)TOKENS * DMODEL];
__device__ __half g_xh [(size_t)TOKENS * DMODEL];
__device__ __half g_ch [(size_t)TOKENS * DMODEL];
__device__ __half g_wh [4][(size_t)DMODEL * DMODEL];   // wq|wk|wv|wo fp16

// ---------------------------------------------------------------------------
__device__ __forceinline__ uint32_t smem_u32(const void* p) {
    uint32_t a;
    asm("{ .reg .u64 t; cvta.to.shared.u64 t, %1; cvt.u32.u64 %0, t; }"
        : "=r"(a) : "l"(p));
    return a;
}

__device__ __forceinline__ void ldsm_x4(uint32_t (&r)[4], uint32_t addr) {
    asm volatile("ldmatrix.sync.aligned.m8n8.x4.shared.b16 {%0,%1,%2,%3}, [%4];"
                 : "=r"(r[0]), "=r"(r[1]), "=r"(r[2]), "=r"(r[3]) : "r"(addr));
}

__device__ __forceinline__ void mma_f16(float (&d)[4], const uint32_t (&a)[4],
                                        const uint32_t* b) {
    asm volatile(
        "mma.sync.aligned.m16n8k16.row.col.f32.f16.f16.f32 "
        "{%0,%1,%2,%3}, {%4,%5,%6,%7}, {%8,%9}, {%0,%1,%2,%3};"
        : "+f"(d[0]), "+f"(d[1]), "+f"(d[2]), "+f"(d[3])
        : "r"(a[0]), "r"(a[1]), "r"(a[2]), "r"(a[3]), "r"(b[0]), "r"(b[1]));
}

__device__ __forceinline__ void cp16(uint32_t dst, const void* src) {
    asm volatile("cp.async.cg.shared.global [%0], [%1], 16;"
                 :: "r"(dst), "l"(src));
}

// ---------------------------------------------------------------------------
// fp32 -> fp16 converts
// ---------------------------------------------------------------------------
__global__ void conv_f16(const float* __restrict__ src,
                         __half* __restrict__ dst, int n4) {
    int i = blockIdx.x * blockDim.x + threadIdx.x;
    if (i >= n4) return;
    float4 v = reinterpret_cast<const float4*>(src)[i];
    __half h[4] = { __float2half_rn(v.x), __float2half_rn(v.y),
                    __float2half_rn(v.z), __float2half_rn(v.w) };
    reinterpret_cast<uint2*>(dst)[i] = *reinterpret_cast<uint2*>(h);
}

__global__ void conv_w4(const float* __restrict__ w0, const float* __restrict__ w1,
                        const float* __restrict__ w2, const float* __restrict__ w3,
                        __half* __restrict__ dst, int n4) {
    int i = blockIdx.x * blockDim.x + threadIdx.x;
    if (i >= n4) return;
    const float* src = (blockIdx.y == 0) ? w0 : (blockIdx.y == 1) ? w1
                     : (blockIdx.y == 2) ? w2 : w3;
    float4 v = reinterpret_cast<const float4*>(src)[i];
    __half h[4] = { __float2half_rn(v.x), __float2half_rn(v.y),
                    __float2half_rn(v.z), __float2half_rn(v.w) };
    reinterpret_cast<uint2*>(dst + (size_t)blockIdx.y * DMODEL * DMODEL)[i] =
        *reinterpret_cast<uint2*>(h);
}

// ---------------------------------------------------------------------------
// HMMA GEMM core: CTA 128x128, 4 warps (2 M x 2 N), warp tile 64x64.
// K-chunk 64, 3-stage cp.async. __launch_bounds__(128, 2): 2 CTAs/SM so the
// two CTAs' load/barrier phases interleave and cover each other's MMA bubbles.
// ---------------------------------------------------------------------------
#define CHUNK       64
#define NCHUNK      (GK / CHUNK)          // 16
#define A_BYTES     16384                 // 128 x 128B
#define W_BYTES     16384                 // 128 x 128B
#define STAGE_BYTES (A_BYTES + W_BYTES)   // 32768
#define NSTAGE      3
#define SMEM_DYN    (NSTAGE * STAGE_BYTES)  // 98304

template <typename OutT>
__device__ __forceinline__ void gemm_core(
    const __half* __restrict__ Ah, const __half* __restrict__ Wh,
    const float* __restrict__ bias, OutT* __restrict__ C,
    int colN0, size_t rowM0, char* smem)
{
    const uint32_t sb = smem_u32(smem);
    const int tid  = threadIdx.x;
    const int wid  = tid >> 5;
    const int lane = tid & 31;
    const int wm   = wid & 1;          // 2 warp rows x 64 M
    const int wn   = wid >> 1;         // 2 warp cols x 64 N

    const char* srcA = (const char*)(Ah + rowM0 * GK);
    const char* srcW = (const char*)(Wh + (size_t)colN0 * GK);

    const int a_row = wm * 64 + (lane & 15);
    const int a_ku  = lane >> 4;
    const int b_row = wn * 64 + (lane & 7) + ((lane >> 4) << 3);
    const int b_ku  = (lane >> 3) & 1;

    float acc[4][8][4];
#pragma unroll
    for (int mi = 0; mi < 4; mi++)
#pragma unroll
        for (int nf = 0; nf < 8; nf++)
#pragma unroll
            for (int j = 0; j < 4; j++) acc[mi][nf][j] = 0.f;

    // loader: 16 x 16B per thread per chunk (A: 1024 units, W: 1024 units)
    auto load_chunk = [&](int c) {
        const uint32_t stage = sb + (c % NSTAGE) * STAGE_BYTES;
        const int k0b = c * CHUNK * 2;
#pragma unroll
        for (int u2 = 0; u2 < 16; u2++) {
            const int g   = tid + u2 * 128;   // 0..2047
            const int t   = g >> 10;          // 0 = A, 1 = W
            const int w   = g & 1023;
            const int row = w >> 3;
            const int u   = w & 7;
            const uint32_t dst = stage + t * A_BYTES + row * 128
                               + ((u ^ (row & 7)) << 4);
            const char* src = (t == 0) ? srcA : srcW;
            cp16(dst, src + (size_t)row * 2048 + k0b + u * 16);
        }
        asm volatile("cp.async.commit_group;" ::: "memory");
    };

    load_chunk(0);
    load_chunk(1);

    for (int c = 0; c < NCHUNK; c++) {
        if (c + 2 < NCHUNK) {
            load_chunk(c + 2);
            asm volatile("cp.async.wait_group 2;" ::: "memory");
        } else if (c + 1 < NCHUNK) {
            asm volatile("cp.async.wait_group 1;" ::: "memory");
        } else {
            asm volatile("cp.async.wait_group 0;" ::: "memory");
        }
        __syncthreads();

        const uint32_t stage = sb + (c % NSTAGE) * STAGE_BYTES;
        const uint32_t t_ah = stage;
        const uint32_t t_wh = stage + A_BYTES;

#pragma unroll
        for (int ks = 0; ks < 4; ks++) {
            uint32_t ah[4][4];
#pragma unroll
            for (int mi = 0; mi < 4; mi++) {
                const int row = a_row + mi * 16;
                const int u   = ks * 2 + a_ku;
                const uint32_t off = row * 128 + ((u ^ (row & 7)) << 4);
                ldsm_x4(ah[mi], t_ah + off);
            }
            uint32_t bh[4][4];
#pragma unroll
            for (int gg = 0; gg < 4; gg++) {
                const int row = b_row + gg * 16;
                const int u   = ks * 2 + b_ku;
                const uint32_t off = row * 128 + ((u ^ (row & 7)) << 4);
                ldsm_x4(bh[gg], t_wh + off);
            }
#pragma unroll
            for (int mi = 0; mi < 4; mi++)
#pragma unroll
                for (int gg = 0; gg < 4; gg++)
#pragma unroll
                    for (int sub = 0; sub < 2; sub++)
                        mma_f16(acc[mi][gg * 2 + sub], ah[mi], &bh[gg][sub * 2]);
        }
        __syncthreads();
    }

#pragma unroll
    for (int mi = 0; mi < 4; mi++) {
#pragma unroll
        for (int nf = 0; nf < 8; nf++) {
            const int col = colN0 + wn * 64 + nf * 8 + (lane & 3) * 2;
            const float2 bv2 = *reinterpret_cast<const float2*>(bias + col);
#pragma unroll
            for (int rh = 0; rh < 2; rh++) {
                const size_t row = rowM0 + wm * 64 + mi * 16 + (lane >> 2) + rh * 8;
                const float ox = acc[mi][nf][rh * 2 + 0] + bv2.x;
                const float oy = acc[mi][nf][rh * 2 + 1] + bv2.y;
                if constexpr (sizeof(OutT) == 2) {
                    *reinterpret_cast<__half2*>((__half*)C + row * DMODEL + col) =
                        __floats2half2_rn(ox, oy);
                } else {
                    float2 o; o.x = ox; o.y = oy;
                    *reinterpret_cast<float2*>((float*)C + row * DMODEL + col) = o;
                }
            }
        }
    }
}

// Fused QKV projection: grid (24, 256); blockIdx.x -> (weight sel, N tile)
__global__ __launch_bounds__(128, 2) void gemm_qkv(
    const __half* __restrict__ Ah, const __half* __restrict__ Wh,
    const float* __restrict__ bq, const float* __restrict__ bk,
    const float* __restrict__ bv,
    __half* __restrict__ Q, __half* __restrict__ K, __half* __restrict__ V)
{
    extern __shared__ __align__(1024) char smem[];
    const int wsel  = blockIdx.x >> 3;
    const int colN0 = (blockIdx.x & 7) * 128;
    const size_t rowM0 = (size_t)blockIdx.y * 128;
    const size_t WN = (size_t)DMODEL * DMODEL;

    const float* bias = (wsel == 0) ? bq : (wsel == 1) ? bk : bv;
    __half*      C    = (wsel == 0) ? Q  : (wsel == 1) ? K  : V;
    gemm_core<__half>(Ah, Wh + wsel * WN, bias, C, colN0, rowM0, smem);
}

__global__ __launch_bounds__(128, 2) void gemm_out(
    const __half* __restrict__ Ah, const __half* __restrict__ Wh,
    const float* __restrict__ bias, float* __restrict__ C)
{
    extern __shared__ __align__(1024) char smem[];
    gemm_core<float>(Ah, Wh, bias, C, blockIdx.x * 128,
                     (size_t)blockIdx.y * 128, smem);
}

// ---------------------------------------------------------------------------
// Per-token attention — vectorized shared accesses (unchanged from R12).
// ---------------------------------------------------------------------------
__global__ __launch_bounds__(256) void attn_kernel(
    const __half* __restrict__ Q, const __half* __restrict__ K,
    const __half* __restrict__ V, __half* __restrict__ CH)
{
    const size_t base = (size_t)blockIdx.x * DMODEL;
    __shared__ __half sq[DMODEL];
    __shared__ __half sk[DMODEL];
    __shared__ __half sv[DMODEL];
    __shared__ float  sp[NHEAD][NHEAD];

    const int tid = threadIdx.x;
    if (tid < 128) {
        reinterpret_cast<uint4*>(sq)[tid] = reinterpret_cast<const uint4*>(Q + base)[tid];
        reinterpret_cast<uint4*>(sk)[tid] = reinterpret_cast<const uint4*>(K + base)[tid];
    } else {
        reinterpret_cast<uint4*>(sv)[tid - 128] =
            reinterpret_cast<const uint4*>(V + base)[tid - 128];
    }
    __syncthreads();

    const __half2* sq2 = reinterpret_cast<const __half2*>(sq);
    const __half2* sk2 = reinterpret_cast<const __half2*>(sk);
    const __half2* sv2 = reinterpret_cast<const __half2*>(sv);

    const int h    = tid >> 4;
    const int g    = tid & 15;
    const int lane = tid & 31;
    float s = 0.f;
#pragma unroll
    for (int jj = 0; jj < 32; jj++) {
        const int j = (jj + lane) & 31;
        const float2 a = __half22float2(sq2[h * 32 + j]);
        const float2 b = __half22float2(sk2[g * 32 + j]);
        s = fmaf(a.x, b.x, s);
        s = fmaf(a.y, b.y, s);
    }
    s *= 0.125f;

    float m = s;
#pragma unroll
    for (int o = 8; o > 0; o >>= 1) m = fmaxf(m, __shfl_xor_sync(0xFFFFFFFFu, m, o, 16));
    const float e = __expf(s - m);
    float sum = e;
#pragma unroll
    for (int o = 8; o > 0; o >>= 1) sum += __shfl_xor_sync(0xFFFFFFFFu, sum, o, 16);
    sp[h][g] = e / sum;
    __syncthreads();

    __half2* out2 = reinterpret_cast<__half2*>(CH + base);
#pragma unroll
    for (int r = 0; r < 2; r++) {
        const int idx2 = tid + r * 256;
        const int hh   = idx2 >> 5;
        const int d2   = idx2 & 31;
        float pr[16];
        *reinterpret_cast<float4*>(&pr[0])  = *reinterpret_cast<const float4*>(&sp[hh][0]);
        *reinterpret_cast<float4*>(&pr[4])  = *reinterpret_cast<const float4*>(&sp[hh][4]);
        *reinterpret_cast<float4*>(&pr[8])  = *reinterpret_cast<const float4*>(&sp[hh][8]);
        *reinterpret_cast<float4*>(&pr[12]) = *reinterpret_cast<const float4*>(&sp[hh][12]);
        float ax = 0.f, ay = 0.f;
#pragma unroll
        for (int gg = 0; gg < 16; gg++) {
            const float2 v = __half22float2(sv2[gg * 32 + d2]);
            ax = fmaf(pr[gg], v.x, ax);
            ay = fmaf(pr[gg], v.y, ay);
        }
        out2[hh * 32 + d2] = __floats2half2_rn(ax, ay);
    }
}

// ---------------------------------------------------------------------------
extern "C" void kernel_launch(void* const* d_in, const int* in_sizes, int n_in,
                              void* d_out, int out_size)
{
    const float* x  = (const float*)d_in[0];
    const float* wq = (const float*)d_in[1];
    const float* bq = (const float*)d_in[2];
    const float* wk = (const float*)d_in[3];
    const float* bk = (const float*)d_in[4];
    const float* wv = (const float*)d_in[5];
    const float* bv = (const float*)d_in[6];
    const float* wo = (const float*)d_in[7];
    const float* bo = (const float*)d_in[8];
    float* out = (float*)d_out;

    __half *qh, *kh, *vh, *xh, *ch, *wh;
    cudaGetSymbolAddress((void**)&qh, g_qh);
    cudaGetSymbolAddress((void**)&kh, g_kh);
    cudaGetSymbolAddress((void**)&vh, g_vh);
    cudaGetSymbolAddress((void**)&xh, g_xh);
    cudaGetSymbolAddress((void**)&ch, g_ch);
    cudaGetSymbolAddress((void**)&wh, g_wh);

    cudaFuncSetAttribute(gemm_qkv,
                         cudaFuncAttributeMaxDynamicSharedMemorySize, SMEM_DYN);
    cudaFuncSetAttribute(gemm_out,
                         cudaFuncAttributeMaxDynamicSharedMemorySize, SMEM_DYN);

    const size_t WN = (size_t)DMODEL * DMODEL;
    const int nx4 = (TOKENS * DMODEL) / 4;
    const int nw4 = (int)(WN / 4);

    conv_f16<<<(nx4 + 255) / 256, 256>>>(x, xh, nx4);
    dim3 wgrid((nw4 + 255) / 256, 4);
    conv_w4<<<wgrid, 256>>>(wq, wk, wv, wo, wh, nw4);

    dim3 qkvgrid(24, TOKENS / 128);       // 3 weights x 8 N-tiles, 256 M-tiles
    gemm_qkv<<<qkvgrid, 128, SMEM_DYN>>>(xh, wh, bq, bk, bv, qh, kh, vh);

    attn_kernel<<<TOKENS, 256>>>(qh, kh, vh, ch);

    dim3 ogrid(DMODEL / 128, TOKENS / 128);
    gemm_out<<<ogrid, 128, SMEM_DYN>>>(ch, wh + 3 * WN, bo, out);
}